// round 15
// baseline (speedup 1.0000x reference)
#include <cuda_runtime.h>
#include <cuda_fp16.h>
#include <cstdint>

#define NV 65536
#define KK 27
#define CH 128

// tcgen05 fast path only in the arch-specific sm_103a pass (plain compute_103
// rejects tcgen05 in ptxas).
#if defined(__CUDA_ARCH__) && (defined(__CUDA_ARCH_FEAT_SM103_ALL) || \
    (defined(__CUDA_ARCH_SPECIFIC__) && (__CUDA_ARCH_SPECIFIC__ == 1030)))
#define TC_PATH 1
#else
#define TC_PATH 0
#endif

// ---------------- scratch (static __device__, no allocs) ----------------
// g_nbr holds (input_row + 1); 0 means "no neighbor" -> zero-filled via
// cp.async src-size=0 (row 0 of g_f16 is also kept zero as a fallback).
__device__ __align__(256) int    g_nbr[KK * NV];            // 7 MB, zero-init
__device__ __align__(256) __half g_f16[(NV + 1) * CH];      // row 0 = zeros
__device__ __align__(256) __half g_w16[KK * CH * CH];       // 864 KB, per-path layout

// ---------------- common helpers ----------------
__device__ __forceinline__ uint32_t smem_to_u32(const void* smem_ptr) {
    uint32_t addr;
    asm("{ .reg .u64 tmp; cvta.to.shared.u64 tmp, %1; cvt.u32.u64 %0, tmp; }"
        : "=r"(addr) : "l"(smem_ptr));
    return addr;
}

// TC path: hdr + 4 A-half tiles (4x32KB) + 2 W-half stages (2x16KB) = 164864.
#define SMEM_BYTES 164864
#define NTHREADS 288

// cp.async (L1-caching variant) + mbarrier-tracked completion (sm_80+)
#define CP_ASYNC_CA16_SZ(dst, src, sz) \
    asm volatile("cp.async.ca.shared.global [%0], [%1], 16, %2;" \
                 :: "r"((uint32_t)(dst)), "l"(src), "r"((uint32_t)(sz)) : "memory")
#define CP_ASYNC_MBAR_ARRIVE_NOINC(mbar) \
    asm volatile("cp.async.mbarrier.arrive.noinc.shared.b64 [%0];" \
                 :: "r"((uint32_t)(mbar)) : "memory")

#if TC_PATH
// ---------------- tcgen05 / cluster helpers ----------------
__device__ __forceinline__ uint32_t elect_one_pred() {
    uint32_t pred;
    asm volatile(
        "{\n\t.reg .pred p;\n\t"
        "elect.sync _|p, 0xFFFFFFFF;\n\t"
        "selp.b32 %0, 1, 0, p;\n\t}"
        : "=r"(pred));
    return pred;
}
__device__ __forceinline__ uint32_t cluster_ctarank() {
    uint32_t r;
    asm("mov.u32 %0, %%cluster_ctarank;" : "=r"(r));
    return r;
}

#define TCGEN05_ALLOC_CG2(smem_result_addr, nCols) \
    asm volatile("tcgen05.alloc.cta_group::2.sync.aligned.shared::cta.b32 [%0], %1;" \
                 :: "r"((uint32_t)(smem_result_addr)), "r"((uint32_t)(nCols)) : "memory")
#define TCGEN05_DEALLOC_CG2(tmem_addr, nCols) \
    asm volatile("tcgen05.dealloc.cta_group::2.sync.aligned.b32 %0, %1;" \
                 :: "r"(tmem_addr), "r"((uint32_t)(nCols)))
#define TCGEN05_RELINQUISH_CG2() \
    asm volatile("tcgen05.relinquish_alloc_permit.cta_group::2.sync.aligned;")
#define TCGEN05_WAIT_LD() asm volatile("tcgen05.wait::ld.sync.aligned;" ::: "memory")
#define TCGEN05_FENCE_AFTER()  asm volatile("tcgen05.fence::after_thread_sync;" ::: "memory")
#define TCGEN05_COMMIT_MC_CG2(mbar, mask) \
    asm volatile("tcgen05.commit.cta_group::2.mbarrier::arrive::one.shared::cluster.multicast::cluster.b64 [%0], %1;" \
                 :: "r"((uint32_t)(mbar)), "h"((uint16_t)(mask)) : "memory")
#define FENCE_PROXY_ASYNC_SHARED_CTA() \
    asm volatile("fence.proxy.async.shared::cta;" ::: "memory")
#define MBARRIER_INIT(mbar_smem_addr, count) \
    asm volatile("mbarrier.init.shared.b64 [%0], %1;" \
                 :: "r"((uint32_t)(mbar_smem_addr)), "r"((uint32_t)(count)) : "memory")
#define MBARRIER_EXPECT_TX(mbar_smem_addr, tx_bytes) \
    asm volatile("mbarrier.arrive.expect_tx.shared.b64 _, [%0], %1;" \
                 :: "r"((uint32_t)(mbar_smem_addr)), "r"((uint32_t)(tx_bytes)) : "memory")
#define MBARRIER_ARRIVE_CLUSTER(local_mbar_addr, target_rank) \
    asm volatile( \
        "{\n\t.reg .b32 remAddr32;\n\t" \
        "mapa.shared::cluster.u32 remAddr32, %0, %1;\n\t" \
        "mbarrier.arrive.shared::cluster.b64 _, [remAddr32];\n\t}" \
        :: "r"((uint32_t)(local_mbar_addr)), "r"((uint32_t)(target_rank)) : "memory")
#define CP_BULK_G2S(dst_smem, src_gmem, nbytes, mbar_smem_addr) \
    asm volatile("cp.async.bulk.shared::cluster.global.mbarrier::complete_tx::bytes " \
                 "[%0], [%1], %2, [%3];" \
                 :: "r"((uint32_t)(dst_smem)), "l"(src_gmem), "r"((uint32_t)(nbytes)), \
                    "r"((uint32_t)(mbar_smem_addr)) : "memory")
#define CLUSTER_SYNC() do { \
    asm volatile("barrier.cluster.arrive.aligned;" ::: "memory"); \
    asm volatile("barrier.cluster.wait.aligned;" ::: "memory"); \
} while (0)
#define MBARRIER_WAIT_PARITY(mbar_smem_addr, phase_parity) do { \
    uint32_t _mbar = (uint32_t)(mbar_smem_addr); \
    uint32_t _parity = (uint32_t)(phase_parity); \
    uint32_t _done; \
    asm volatile( \
        "{\n\t.reg .pred p;\n\t" \
        "mbarrier.try_wait.parity.acquire.cta.shared::cta.b64 p, [%1], %2;\n\t" \
        "selp.b32 %0, 1, 0, p;\n\t}" \
        : "=r"(_done) : "r"(_mbar), "r"(_parity) : "memory"); \
    if (!_done) { \
        asm volatile( \
            "{\n\t.reg .pred P1;\n\t" \
            "WAIT_LOOP_%=:\n\t" \
            "mbarrier.try_wait.parity.acquire.cta.shared::cta.b64 P1, [%0], %1, 0x989680;\n\t" \
            "@P1 bra.uni WAIT_DONE_%=;\n\t" \
            "bra.uni WAIT_LOOP_%=;\n\t" \
            "WAIT_DONE_%=:\n\t}" \
            :: "r"(_mbar), "r"(_parity) : "memory"); \
    } \
} while(0)

// cg2 SS-mode f16 MMA (M=256 across the pair): 8-reg disable-lane mask.
#define TCGEN05_MMA_F16_SS_CG2(d_tmem, a_desc, b_desc, idesc, enable_d) do { \
    uint32_t _enable = (enable_d) ? 1 : 0; \
    uint32_t _zero = 0; \
    asm volatile( \
        "{\n\t.reg .pred p;\n\t" \
        "setp.ne.u32 p, %6, 0;\n\t" \
        "tcgen05.mma.cta_group::2.kind::f16 [%0], %1, %2, %3, " \
        "{%4, %4, %4, %4, %4, %4, %4, %4}, p;\n\t}" \
        :: "r"(d_tmem), "l"(a_desc), "l"(b_desc), "r"(idesc), \
           "r"(_zero), "r"(_zero), "r"(_enable) \
        : "memory"); \
} while(0)

#define TCGEN05_LD_32X32B_X32(r, tmem_addr) \
    asm volatile( \
        "tcgen05.ld.sync.aligned.32x32b.x32.b32 " \
        "{%0, %1, %2, %3, %4, %5, %6, %7, " \
        " %8, %9, %10, %11, %12, %13, %14, %15, " \
        " %16, %17, %18, %19, %20, %21, %22, %23, " \
        " %24, %25, %26, %27, %28, %29, %30, %31}, [%32];" \
        : "=r"((r)[0]),  "=r"((r)[1]),  "=r"((r)[2]),  "=r"((r)[3]), \
          "=r"((r)[4]),  "=r"((r)[5]),  "=r"((r)[6]),  "=r"((r)[7]), \
          "=r"((r)[8]),  "=r"((r)[9]),  "=r"((r)[10]), "=r"((r)[11]), \
          "=r"((r)[12]), "=r"((r)[13]), "=r"((r)[14]), "=r"((r)[15]), \
          "=r"((r)[16]), "=r"((r)[17]), "=r"((r)[18]), "=r"((r)[19]), \
          "=r"((r)[20]), "=r"((r)[21]), "=r"((r)[22]), "=r"((r)[23]), \
          "=r"((r)[24]), "=r"((r)[25]), "=r"((r)[26]), "=r"((r)[27]), \
          "=r"((r)[28]), "=r"((r)[29]), "=r"((r)[30]), "=r"((r)[31]) \
        : "r"(tmem_addr))

static constexpr uint64_t SMEM_DESC_BASE_SW128 =
    (uint64_t(2) << 61) | (uint64_t(1) << 46) | (uint64_t(64) << 32) | (uint64_t(1) << 16);
#define MAKE_SMEM_DESC(base_addr) \
    (SMEM_DESC_BASE_SW128 | ((uint64_t)((base_addr) >> 4) & 0x3FFF))

// cg2 kind::f16 idesc: f16 inputs, f32 acc, M=256 (16<<24), N=128 (16<<17)
#define MMA_IDESC_CG2 0x10200010u

// SMEM layout (TC): [0] tmem ptr,
// full[t]  @16+8t (cp.async-armed; count 257 on rank0 [+1 remote relay], 256 on rank1)
// empty[t] @48+8t (cg2 multicast commit target, count 1)
// W mbars @80,88, bias @128..640,
// A halves @1024 (4 x 32KB), W-half stages @132096 (2 x 16KB). Total 164864.
// A half-tile: 128 rows x 128 cols fp16; 2 K-slices of 16KB; SW128 atoms.
// W half-image: 64 cout-rows x 128 cols fp16 = 16KB; 2 K-slices of 8KB.
// TMEM: supertile t accumulator D at cols t*128 (this CTA's 128 M-rows).
#define MB_FULL(t)  (16u + (uint32_t)(t) * 8u)
#define MB_EMPTY(t) (48u + (uint32_t)(t) * 8u)
#define MB_WMB(s)   (80u + (uint32_t)(s) * 8u)
#define BIAS_OFF 128
#define A_OFF(t) (1024u + (uint32_t)(t) * 32768u)
#define W_OFF(s) (132096u + (uint32_t)(s) * 16384u)

__global__ void __launch_bounds__(NTHREADS, 1) __cluster_dims__(2, 1, 1)
k_main(const float* __restrict__ bias, float* __restrict__ out) {
    extern __shared__ char smem[];
    uint32_t sb = smem_to_u32(smem);
    int tid = threadIdx.x;
    int wid = tid >> 5;
    int lid = tid & 31;
    uint32_t rank = cluster_ctarank();
    int cbase = (blockIdx.x >> 1) * 1024;          // cluster base row
    int obase = cbase + (int)rank * 128;           // this CTA's rows: obase + t*256 + 0..127

    if (wid == 8) TCGEN05_ALLOC_CG2(sb + 0, 512);
    if (tid == 0) {
        #pragma unroll
        for (int t = 0; t < 4; ++t) {
            MBARRIER_INIT(sb + MB_FULL(t), rank == 0 ? 257 : 256);
            MBARRIER_INIT(sb + MB_EMPTY(t), 1);
        }
        MBARRIER_INIT(sb + MB_WMB(0), 1);
        MBARRIER_INIT(sb + MB_WMB(1), 1);
    }
    if (tid < 128) ((float*)(smem + BIAS_OFF))[tid] = __ldg(&bias[tid]);
    __syncthreads();
    CLUSTER_SYNC();                                 // mbarriers visible cluster-wide
    uint32_t tmem;
    asm volatile("ld.shared.b32 %0, [%1];" : "=r"(tmem) : "r"(sb));
    if (wid == 8) TCGEN05_RELINQUISH_CG2();

    if (tid < 256) {
        // ---- producers: fill this CTA's 128-row half of 4 supertiles ----
        const int c = tid & 15;
        const int row0 = tid >> 4;
        const uint4* fbase = (const uint4*)g_f16 + c;
        uint32_t aswz;
        {
            uint32_t off = ((uint32_t)(c >> 3) << 14)      // 16KB K-slice
                         + (uint32_t)row0 * 128u
                         + (uint32_t)((c & 7) << 4);
            off ^= (off >> 3) & 0x70u;                     // SW128 swizzle
            aswz = off;
        }
        int nbR[32];
        {
            const int* nbk = g_nbr + 0 * NV + obase + row0;
            #pragma unroll
            for (int t = 0; t < 4; ++t)
                #pragma unroll
                for (int j = 0; j < 8; ++j)
                    nbR[t * 8 + j] = __ldg(nbk + t * 256 + 16 * j);
        }
        for (int k = 0; k < KK; ++k) {
            #pragma unroll
            for (int t = 0; t < 4; ++t) {
                if (k >= 1) MBARRIER_WAIT_PARITY(sb + MB_EMPTY(t), (k - 1) & 1);
                uint32_t As = sb + A_OFF(t) + aswz;
                #pragma unroll
                for (int j = 0; j < 8; ++j) {
                    int nb = nbR[t * 8 + j];
                    uint32_t sz = nb ? 16u : 0u;
                    CP_ASYNC_CA16_SZ(As + (uint32_t)j * 2048u,
                                     fbase + (size_t)nb * 16, sz);
                }
                CP_ASYNC_MBAR_ARRIVE_NOINC(sb + MB_FULL(t));
            }
            if (k + 1 < KK) {
                const int* nbk = g_nbr + (k + 1) * NV + obase + row0;
                #pragma unroll
                for (int t = 0; t < 4; ++t)
                    #pragma unroll
                    for (int j = 0; j < 8; ++j)
                        nbR[t * 8 + j] = __ldg(nbk + t * 256 + 16 * j);
            }
        }
        // ---- per-tile early epilogue (this CTA's rows of each supertile) ----
        const float* bsm = (const float*)(smem + BIAS_OFF);
        #pragma unroll
        for (int pass = 0; pass < 2; ++pass) {
            int t = pass * 2 + (wid >> 2);
            MBARRIER_WAIT_PARITY(sb + MB_EMPTY(t), 0);   // 27th commit (i=26)
            TCGEN05_FENCE_AFTER();
            int row = obase + t * 256 + (wid & 3) * 32 + lid;
            uint32_t cbaseT = (uint32_t)(t * 128);
            float* orow = out + (size_t)row * CH;
            #pragma unroll
            for (int b = 0; b < 128; b += 32) {
                uint32_t d[32];
                TCGEN05_LD_32X32B_X32(d, tmem + cbaseT + (uint32_t)b);
                TCGEN05_WAIT_LD();
                #pragma unroll
                for (int cc = 0; cc < 32; cc += 4) {
                    float4 v;
                    v.x = __uint_as_float(d[cc + 0]) + bsm[b + cc + 0];
                    v.y = __uint_as_float(d[cc + 1]) + bsm[b + cc + 1];
                    v.z = __uint_as_float(d[cc + 2]) + bsm[b + cc + 2];
                    v.w = __uint_as_float(d[cc + 3]) + bsm[b + cc + 3];
                    *(float4*)(orow + b + cc) = v;
                }
            }
        }
    } else {
        // ---- leader warp: W-half prefetch + (rank0: cg2 MMA | rank1: relay) ----
        uint32_t lead = elect_one_pred();
        const char* wsrc = (const char*)g_w16 + (size_t)rank * 16384;
        if (lead) {
            MBARRIER_EXPECT_TX(sb + MB_WMB(0), 16384);
            CP_BULK_G2S(sb + W_OFF(0), wsrc, 16384, sb + MB_WMB(0));
            MBARRIER_EXPECT_TX(sb + MB_WMB(1), 16384);
            CP_BULK_G2S(sb + W_OFF(1), wsrc + 32768, 16384, sb + MB_WMB(1));
        }
        for (int k = 0; k < KK; ++k) {
            int s = k & 1;
            MBARRIER_WAIT_PARITY(sb + MB_WMB(s), (k >> 1) & 1);
            if (rank == 0) {
                uint64_t bd = MAKE_SMEM_DESC(sb + W_OFF(s));
                #pragma unroll
                for (int t = 0; t < 4; ++t) {
                    MBARRIER_WAIT_PARITY(sb + MB_FULL(t), k & 1);  // 256 local + relay
                    FENCE_PROXY_ASYNC_SHARED_CTA();
                    TCGEN05_FENCE_AFTER();
                    if (lead) {
                        uint64_t ad = MAKE_SMEM_DESC(sb + A_OFF(t));
                        #pragma unroll
                        for (int ks = 0; ks < 8; ++ks) {
                            // A: K-slice1 at 16KB = 1024 units
                            uint64_t aoff = (ks < 4) ? (uint64_t)(2 * ks)
                                                     : (uint64_t)(1024 + 2 * (ks - 4));
                            // B half: K-slice1 at 8KB = 512 units
                            uint64_t boff = (ks < 4) ? (uint64_t)(2 * ks)
                                                     : (uint64_t)(512 + 2 * (ks - 4));
                            TCGEN05_MMA_F16_SS_CG2(tmem + (uint32_t)(t * 128),
                                                   ad + aoff, bd + boff, MMA_IDESC_CG2,
                                                   !(k == 0 && ks == 0));
                        }
                        TCGEN05_COMMIT_MC_CG2(sb + MB_EMPTY(t), 0x3);
                    }
                }
            } else {
                // rank 1: relay local fill-completion to rank0's full[t]
                #pragma unroll
                for (int t = 0; t < 4; ++t) {
                    MBARRIER_WAIT_PARITY(sb + MB_FULL(t), k & 1);  // 256 local
                    FENCE_PROXY_ASYNC_SHARED_CTA();                 // publish fills
                    if (lead) MBARRIER_ARRIVE_CLUSTER(sb + MB_FULL(t), 0);
                }
            }
            // reissue W(k+2) half into stage s after this k's MMAs complete
            if (k + 2 < KK) {
                MBARRIER_WAIT_PARITY(sb + MB_EMPTY(3), k & 1);
                if (lead) {
                    MBARRIER_EXPECT_TX(sb + MB_WMB(s), 16384);
                    CP_BULK_G2S(sb + W_OFF(s), wsrc + (size_t)(k + 2) * 32768,
                                16384, sb + MB_WMB(s));
                }
            }
        }
    }
    __syncthreads();
    if (wid == 8) TCGEN05_DEALLOC_CG2(tmem, 512);
    CLUSTER_SYNC();
}

#else  // ---------------- mma.sync fallback path (512 rows via 4 halves) -------
#define A_FB(w)  ((w) * 4096)
#define W_FB     32768
#define BIAS_FB  65536

__device__ __forceinline__ void mma16816(float* c, uint32_t a0, uint32_t a1,
                                         uint32_t a2, uint32_t a3,
                                         uint32_t b0, uint32_t b1) {
    asm volatile(
        "mma.sync.aligned.m16n8k16.row.col.f32.f16.f16.f32 "
        "{%0,%1,%2,%3}, {%4,%5,%6,%7}, {%8,%9}, {%0,%1,%2,%3};"
        : "+f"(c[0]), "+f"(c[1]), "+f"(c[2]), "+f"(c[3])
        : "r"(a0), "r"(a1), "r"(a2), "r"(a3), "r"(b0), "r"(b1));
}

__global__ void __launch_bounds__(NTHREADS)
k_main(const float* __restrict__ bias, float* __restrict__ out) {
    extern __shared__ char smem[];
    uint32_t sb = smem_to_u32(smem);
    int tid = threadIdx.x;
    int wid = tid >> 5;
    int lane = tid & 31;

    if (tid < 128) ((float*)(smem + BIAS_FB))[tid] = __ldg(&bias[tid]);

    int m = lane >> 3, rl = lane & 7;
    int lrow = rl + ((m & 1) << 3);

    for (int half = 0; half < 4; ++half) {
        int o0 = blockIdx.x * 512 + half * 128;
        float acc[16][4] = {};
        for (int k = 0; k < KK; ++k) {
            __syncthreads();
            if (tid < 256) {
                int nbl = (lane < 16) ? __ldg(&g_nbr[k * NV + o0 + wid * 16 + lane]) : 0;
                char* ab = smem + A_FB(wid);
                #pragma unroll
                for (int i = 0; i < 8; ++i) {
                    int row = i * 2 + (lane >> 4);
                    int rn = __shfl_sync(0xffffffffu, nbl, row);
                    uint4 v = __ldg((const uint4*)(g_f16 + (size_t)rn * CH) + (lane & 15));
                    int c = lane & 15;
                    *(uint4*)(ab + row * 256 + ((c ^ (row & 7)) << 4)) = v;
                }
                // fallback W layout: [k][half(cout>>6)][16KB image]; rebuild linear reads
                const uint4* ws = (const uint4*)((const char*)g_w16 + (size_t)k * 32768)
                                  + wid * 256 + lane;
                uint4* wd = (uint4*)(smem + W_FB) + wid * 256 + lane;
                #pragma unroll
                for (int i = 0; i < 8; ++i) wd[i * 32] = __ldg(ws + i * 32);
            }
            __syncthreads();
            if (tid < 256) {
                uint32_t ab32 = sb + A_FB(wid);
                uint32_t wb32 = sb + W_FB;
                uint32_t arow = ab32 + (uint32_t)lrow * 256u;
                #pragma unroll
                for (int kt = 0; kt < 8; ++kt) {
                    int chunk = kt * 2 + (m >> 1);
                    uint32_t aaddr = arow + (uint32_t)((chunk ^ (lrow & 7)) << 4);
                    uint32_t a0, a1, a2, a3;
                    asm volatile(
                        "ldmatrix.sync.aligned.m8n8.x4.shared.b16 {%0,%1,%2,%3}, [%4];"
                        : "=r"(a0), "=r"(a1), "=r"(a2), "=r"(a3) : "r"(aaddr));
                    #pragma unroll
                    for (int nt = 0; nt < 16; ++nt) {
                        uint32_t baddr = wb32 + (uint32_t)((((kt << 4) + nt) << 8) + (lane << 3));
                        uint32_t b0, b1;
                        asm volatile("ld.shared.v2.b32 {%0,%1}, [%2];"
                                     : "=r"(b0), "=r"(b1) : "r"(baddr));
                        mma16816(acc[nt], a0, a1, a2, a3, b0, b1);
                    }
                }
            }
        }
        if (tid < 256) {
            int gid = lane >> 2, tig = lane & 3;
            const float* bsm = (const float*)(smem + BIAS_FB);
            size_t r0 = (size_t)(o0 + wid * 16 + gid);
            #pragma unroll
            for (int nt = 0; nt < 16; ++nt) {
                int col = nt * 8 + tig * 2;
                float2 bv = *(const float2*)(bsm + col);
                float2 v0 = make_float2(acc[nt][0] + bv.x, acc[nt][1] + bv.y);
                float2 v1 = make_float2(acc[nt][2] + bv.x, acc[nt][3] + bv.y);
                *(float2*)(out + r0 * CH + col) = v0;
                *(float2*)(out + (r0 + 8) * CH + col) = v1;
            }
        }
        __syncthreads();
    }
}
#endif  // TC_PATH

// ---------------- fused prep kernel ----------------
// blocks [0, 6912): rulebook scatter (g_nbr = in_idx+1)
// blocks [6912, 15104): feature fp16 convert, float4-vectorized (+1 row shift)
// blocks [15104, 16832): weight pack (per-path layout)
#define PREP_BLOCKS 16832

__global__ void k_prep(const float* __restrict__ f, const float* __restrict__ w,
                       const int* __restrict__ in_idx, const int* __restrict__ out_idx) {
    int b = blockIdx.x;
    if (b < 6912) {
        int i = b * 256 + threadIdx.x;            // [0, KK*NV)
        int o = out_idx[i];
        if (o < NV) g_nbr[(i / NV) * NV + o] = in_idx[i] + 1;
    } else if (b < 15104) {
        int i = (b - 6912) * 256 + threadIdx.x;   // [0, NV*32) float4 words
        float4 v = ((const float4*)f)[i];
        __half2 h0, h1;
        h0.x = __float2half_rn(v.x); h0.y = __float2half_rn(v.y);
        h1.x = __float2half_rn(v.z); h1.y = __float2half_rn(v.w);
        uint2 pk;
        pk.x = *(uint32_t*)&h0; pk.y = *(uint32_t*)&h1;
        ((uint2*)g_f16)[i + 32] = pk;             // +1 row shift (row 0 stays zero)
    } else {
        int i = (b - 15104) * 256 + threadIdx.x;
#if TC_PATH
        // W[k][cin][cout] -> per-half SW128 blocked images:
        // [k][half = cout>>6][16KB: 64 rows x 128 cols fp16]
        if (i >= KK * CH * CH) return;
        int k = i >> 14;
        int r = (i >> 7) & 127;   // c_out (N row)
        int c = i & 127;          // c_in  (K col)
        float v = w[(k << 14) + (c << 7) + r];
        uint32_t half = (uint32_t)(r >> 6);
        uint32_t rh = (uint32_t)(r & 63);
        // half-image: atom = 8 rows x 64 fp16 (128B); 8 atom-rows, 2 atom-cols (K slices)
        uint32_t atom = (rh >> 3) + ((uint32_t)(c >> 6) << 3);
        uint32_t off = atom * 1024u + (rh & 7) * 128u + (uint32_t)(c & 63) * 2u;
        off ^= (off >> 3) & 0x70u;
        g_w16[((uint32_t)k * 32768u + half * 16384u + off) >> 1] = __float2half_rn(v);
#else
        // mma.sync B-fragment-ready image: [k][ktile(8)][ntile(16)][lane(32)][reg(2)] u32
        if (i >= KK * 8 * 16 * 32 * 2) return;
        int reg   = i & 1;
        int lane  = (i >> 1) & 31;
        int nt    = (i >> 6) & 15;
        int ktile = (i >> 10) & 7;
        int k     = i >> 13;
        int tig = lane & 3, gid = lane >> 2;
        int n    = nt * 8 + gid;
        int cin0 = ktile * 16 + tig * 2 + reg * 8;
        float w0 = w[(k * CH + cin0) * CH + n];
        float w1 = w[(k * CH + cin0 + 1) * CH + n];
        __half2 h;
        h.x = __float2half_rn(w0);
        h.y = __float2half_rn(w1);
        ((__half2*)g_w16)[i] = h;
#endif
    }
}

// ---------------- launch ----------------
extern "C" void kernel_launch(void* const* d_in, const int* in_sizes, int n_in,
                              void* d_out, int out_size) {
    const float* features = (const float*)d_in[0];
    const float* weight   = (const float*)d_in[1];
    const float* bias     = (const float*)d_in[2];
    const int*   in_idx   = (const int*)d_in[3];
    const int*   out_idx  = (const int*)d_in[4];
    float*       out      = (float*)d_out;

    cudaFuncSetAttribute(k_main, cudaFuncAttributeMaxDynamicSharedMemorySize, SMEM_BYTES);

    k_prep<<<PREP_BLOCKS, 256>>>(features, weight, in_idx, out_idx);
    k_main<<<NV / 512, NTHREADS, SMEM_BYTES>>>(bias, out);
}